// round 7
// baseline (speedup 1.0000x reference)
#include <cuda_runtime.h>
#include <cuda_bf16.h>
#include <cstdint>

#define NRV  40962
#define NHV  163842
#define NR7V 286734
#define M1   81924
#define M2   327684

// ---------------- scratch ----------------
__device__ __nv_bfloat16 g_x1h[(size_t)M1*128], g_x1l[(size_t)M1*128];
__device__ float         g_h  [(size_t)M1*448];
__device__ __nv_bfloat16 g_xh [(size_t)M2*128], g_xl [(size_t)M2*128];
__device__ float         g_t1 [(size_t)M2*64];
__device__ __nv_bfloat16 g_y1h[(size_t)M2*64],  g_y1l[(size_t)M2*64];
__device__ float         g_t2 [(size_t)M2*64];
__device__ __nv_bfloat16 g_Wuh[128*448], g_Wul[128*448];
__device__ __nv_bfloat16 g_W1h[896*64],  g_W1l[896*64];
__device__ __nv_bfloat16 g_W2h[448*64],  g_W2l[448*64];
__device__ double        g_st[256];
__device__ float         g_sc1[64], g_bb1[64], g_sc2[64], g_bb2[64];

__device__ __forceinline__ void bsplit(float v, __nv_bfloat16& hi, __nv_bfloat16& lo) {
    hi = __float2bfloat16(v);
    lo = __float2bfloat16(v - __bfloat162float(hi));
}
__device__ __forceinline__ unsigned pk2(__nv_bfloat16 a, __nv_bfloat16 b) {
    return (unsigned)__bfloat16_as_ushort(a) | ((unsigned)__bfloat16_as_ushort(b) << 16);
}

// ---------------- PTX helpers ----------------
#define LDSM4(d0,d1,d2,d3,addr) \
    asm volatile("ldmatrix.sync.aligned.m8n8.x4.shared.b16 {%0,%1,%2,%3}, [%4];" \
                 : "=r"(d0),"=r"(d1),"=r"(d2),"=r"(d3) : "r"(addr))
#define LDSM4T(d0,d1,d2,d3,addr) \
    asm volatile("ldmatrix.sync.aligned.m8n8.x4.trans.shared.b16 {%0,%1,%2,%3}, [%4];" \
                 : "=r"(d0),"=r"(d1),"=r"(d2),"=r"(d3) : "r"(addr))
#define MMA_BF16(c,a0,a1,a2,a3,b0,b1) \
    asm volatile("mma.sync.aligned.m16n8k16.row.col.f32.bf16.bf16.f32 " \
                 "{%0,%1,%2,%3}, {%4,%5,%6,%7}, {%8,%9}, {%0,%1,%2,%3};" \
                 : "+f"(c[0]),"+f"(c[1]),"+f"(c[2]),"+f"(c[3]) \
                 : "r"(a0),"r"(a1),"r"(a2),"r"(a3),"r"(b0),"r"(b1))

__device__ __forceinline__ void cpa16(uint32_t d, const void* s) {
    asm volatile("cp.async.ca.shared.global [%0], [%1], 16;" :: "r"(d), "l"(s) : "memory");
}
#define CP_COMMIT() asm volatile("cp.async.commit_group;" ::: "memory")
#define CP_WAIT1()  asm volatile("cp.async.wait_group 1;" ::: "memory")

// smem per stage (49152 B):
//   A_hi [0,20480) 256 rows pitch 80 (64B data), A_lo [20480,40960)
//   B_hi [40960,45056) 32 rows x 128B XOR-swizzled, B_lo [45056,49152)
#define STG    49152
#define SMEMSZ (2 * STG)

// ---------------- pipelined 3-term bf16 HMMA GEMM ----------------
// CTA: 256 thr, tile 256(M) x 64(N); warp w covers rows [32w,32w+32) x all 64 cols.
template<int K, int SEG, bool GATHER>
__global__ __launch_bounds__(256, 2)
void bf_gemm(const __nv_bfloat16* __restrict__ Ah, const __nv_bfloat16* __restrict__ Al,
             const __nv_bfloat16* __restrict__ Bh, const __nv_bfloat16* __restrict__ Bl,
             const float* __restrict__ bias, float* __restrict__ out,
             int Mtot, int Ntot, const int* __restrict__ neigh)
{
    extern __shared__ __align__(128) uint8_t sm[];
    constexpr int NC = K / 32;
    const uint32_t smA = (uint32_t)__cvta_generic_to_shared(sm);
    const int tid = threadIdx.x;
    const int colBase = blockIdx.x * 64;
    const int rowCTA  = blockIdx.y * 256;

    // ---- loader roles: 1 thread per A row (256 rows) ----
    const int arow = tid;
    const int gr   = rowCTA + arow;
    const int grC  = gr < Mtot ? gr : Mtot - 1;
    int bOff = 0, n7 = 0;
    if (GATHER) { bOff = (grC >= NHV) ? NHV : 0; n7 = (grC - bOff) * 7; }
    const int bterm = tid >> 7;                  // 0: hi, 1: lo
    const int bk    = (tid & 127) >> 2;          // B k-row 0..31
    const int bg2   = tid & 3;                   // 2 chunks each
    const __nv_bfloat16* Bsrc = bterm ? Bl : Bh;

    const uint32_t aD = smA + arow * 80;
    uint32_t bD[2];
#pragma unroll
    for (int j = 0; j < 2; j++) {
        int chunk = bg2 * 2 + j;
        bD[j] = smA + 40960 + bterm * 4096 + bk * 128 + 16 * (chunk ^ (bk & 7));
    }

#define ISSUE(c_) do { \
        const uint32_t so_ = ((c_) & 1) * STG; \
        int seg_, coff_; \
        if (SEG == 128) { seg_ = (c_) >> 2; coff_ = ((c_) & 3) * 32; } \
        else            { seg_ = (c_) >> 1; coff_ = ((c_) & 1) * 32; } \
        size_t src_ = GATHER ? (size_t)(bOff + neigh[n7 + seg_]) : (size_t)grC; \
        const __nv_bfloat16* pa_ = Ah + src_ * SEG + coff_; \
        const __nv_bfloat16* pl_ = Al + src_ * SEG + coff_; \
        cpa16(aD + so_ +  0, pa_);      cpa16(aD + so_ + 16, pa_ + 8); \
        cpa16(aD + so_ + 32, pa_ + 16); cpa16(aD + so_ + 48, pa_ + 24); \
        cpa16(aD + so_ + 20480 +  0, pl_);      cpa16(aD + so_ + 20480 + 16, pl_ + 8); \
        cpa16(aD + so_ + 20480 + 32, pl_ + 16); cpa16(aD + so_ + 20480 + 48, pl_ + 24); \
        const __nv_bfloat16* pb_ = Bsrc + (size_t)((c_) * 32 + bk) * Ntot + colBase; \
        cpa16(bD[0] + so_, pb_ + (bg2 * 2 + 0) * 8); \
        cpa16(bD[1] + so_, pb_ + (bg2 * 2 + 1) * 8); \
    } while (0)

    // ---- compute roles ----
    const int lane = tid & 31, w = tid >> 5;
    const uint32_t aL = smA + (w * 32 + (lane & 15)) * 80 + (lane >> 4) * 16;
    const int nH  = lane >> 4;
    const int krl = lane & 15;
    const int swz = krl & 7;

    float acc[2][8][4];
#pragma unroll
    for (int a = 0; a < 2; a++)
#pragma unroll
        for (int b = 0; b < 8; b++)
#pragma unroll
            for (int q = 0; q < 4; q++) acc[a][b][q] = 0.f;

    ISSUE(0); CP_COMMIT();
    if (NC > 1) ISSUE(1);
    CP_COMMIT();

#pragma unroll 1
    for (int c = 0; c < NC; c++) {
        CP_WAIT1();
        __syncthreads();

        const uint32_t so = (c & 1) * STG;
#pragma unroll
        for (int kk = 0; kk < 2; kk++) {
            uint32_t ah[2][4], al[2][4];
#pragma unroll
            for (int mh = 0; mh < 2; mh++) {
                uint32_t aAddr = aL + so + mh * (16 * 80) + kk * 32;
                LDSM4(ah[mh][0], ah[mh][1], ah[mh][2], ah[mh][3], aAddr);
                LDSM4(al[mh][0], al[mh][1], al[mh][2], al[mh][3], aAddr + 20480);
            }
            const uint32_t bRow = smA + so + 40960 + (kk * 16 + krl) * 128;
#pragma unroll
            for (int bt = 0; bt < 4; bt++) {
                uint32_t bh0, bh1, bh2, bh3, bl0, bl1, bl2, bl3;
                uint32_t bAddr = bRow + 16 * ((2 * bt + nH) ^ swz);
                LDSM4T(bh0, bh1, bh2, bh3, bAddr);
                LDSM4T(bl0, bl1, bl2, bl3, bAddr + 4096);
#pragma unroll
                for (int mh = 0; mh < 2; mh++) {
                    MMA_BF16(acc[mh][2*bt],   ah[mh][0],ah[mh][1],ah[mh][2],ah[mh][3], bh0,bh1);
                    MMA_BF16(acc[mh][2*bt],   ah[mh][0],ah[mh][1],ah[mh][2],ah[mh][3], bl0,bl1);
                    MMA_BF16(acc[mh][2*bt],   al[mh][0],al[mh][1],al[mh][2],al[mh][3], bh0,bh1);
                    MMA_BF16(acc[mh][2*bt+1], ah[mh][0],ah[mh][1],ah[mh][2],ah[mh][3], bh2,bh3);
                    MMA_BF16(acc[mh][2*bt+1], ah[mh][0],ah[mh][1],ah[mh][2],ah[mh][3], bl2,bl3);
                    MMA_BF16(acc[mh][2*bt+1], al[mh][0],al[mh][1],al[mh][2],al[mh][3], bh2,bh3);
                }
            }
        }
        __syncthreads();
        if (c + 2 < NC) ISSUE(c + 2);
        CP_COMMIT();
    }
#undef ISSUE

    // ---- epilogue ----
    const int gid = lane >> 2, tig = lane & 3;
#pragma unroll
    for (int mh = 0; mh < 2; mh++) {
        const int r0 = rowCTA + w * 32 + mh * 16 + gid;
#pragma unroll
        for (int j = 0; j < 8; j++) {
            const int col = colBase + j * 8 + tig * 2;
            const float b0 = bias[col], b1 = bias[col + 1];
            if (r0 < Mtot)
                *(float2*)(out + (size_t)r0 * Ntot + col) =
                    make_float2(acc[mh][j][0] + b0, acc[mh][j][1] + b1);
            if (r0 + 8 < Mtot)
                *(float2*)(out + (size_t)(r0 + 8) * Ntot + col) =
                    make_float2(acc[mh][j][2] + b0, acc[mh][j][3] + b1);
        }
    }
}

// ---------------- aux kernels ----------------
__global__ void prep_k(const float* __restrict__ x1, const float* __restrict__ upW,
                       const float* __restrict__ c1W, const float* __restrict__ c2W)
{
    int i = blockIdx.x * blockDim.x + threadIdx.x;
    if (i < 256) g_st[i] = 0.0;
    const int stride = gridDim.x * blockDim.x;
    for (int t = i; t < M1 * 128; t += stride) {
        __nv_bfloat16 a, b; bsplit(x1[t], a, b); g_x1h[t] = a; g_x1l[t] = b;
    }
    for (int t = i; t < 128 * 448; t += stride) {
        __nv_bfloat16 a, b; bsplit(upW[t], a, b); g_Wuh[t] = a; g_Wul[t] = b;
    }
    for (int t = i; t < 896 * 64; t += stride) {
        __nv_bfloat16 a, b; bsplit(c1W[t], a, b); g_W1h[t] = a; g_W1l[t] = b;
    }
    for (int t = i; t < 448 * 64; t += stride) {
        __nv_bfloat16 a, b; bsplit(c2W[t], a, b); g_W2h[t] = a; g_W2l[t] = b;
    }
}

__global__ void build_x_k(const float* __restrict__ h, const float* __restrict__ x2,
                          const int* __restrict__ topIdx, const int* __restrict__ downIdx)
{
    int idx = blockIdx.x * 256 + threadIdx.x;
    if (idx >= M2 * 32) return;
    int row = idx >> 5, q = idx & 31;
    int b = (row >= NHV) ? 1 : 0;
    int n = row - b * NHV;
    float4 v;
    if (q < 16) {
        int c = q * 4;
        if (n < NRV) {
            v = *(const float4*)(h + ((size_t)b * NR7V + topIdx[n]) * 64 + c);
        } else {
            int m = n - NRV;
            float4 v0 = *(const float4*)(h + ((size_t)b * NR7V + downIdx[2*m])   * 64 + c);
            float4 v1 = *(const float4*)(h + ((size_t)b * NR7V + downIdx[2*m+1]) * 64 + c);
            v = make_float4(0.5f*(v0.x+v1.x), 0.5f*(v0.y+v1.y), 0.5f*(v0.z+v1.z), 0.5f*(v0.w+v1.w));
        }
    } else {
        v = *(const float4*)(x2 + (size_t)row * 64 + (q - 16) * 4);
    }
    size_t o = (size_t)row * 128 + q * 4;
    __nv_bfloat16 h0,l0,h1,l1,h2,l2,h3,l3;
    bsplit(v.x,h0,l0); bsplit(v.y,h1,l1); bsplit(v.z,h2,l2); bsplit(v.w,h3,l3);
    *(uint2*)(g_xh + o) = make_uint2(pk2(h0,h1), pk2(h2,h3));
    *(uint2*)(g_xl + o) = make_uint2(pk2(l0,l1), pk2(l2,l3));
}

__global__ void stats_k(const float* __restrict__ t, double* __restrict__ st)
{
    int c   = threadIdx.x & 63;
    int sub = threadIdx.x >> 6;
    double s = 0.0, sq = 0.0;
    for (int r = blockIdx.x * 4 + sub; r < M2; r += gridDim.x * 4) {
        float v = t[(size_t)r * 64 + c];
        s += v; sq += (double)v * (double)v;
    }
    __shared__ double sh[512];
    sh[threadIdx.x] = s; sh[256 + threadIdx.x] = sq;
    __syncthreads();
    if (sub == 0) {
#pragma unroll
        for (int i = 1; i < 4; i++) { s += sh[c + 64 * i]; sq += sh[256 + c + 64 * i]; }
        atomicAdd(&st[c], s);
        atomicAdd(&st[64 + c], sq);
    }
}

__global__ void finalize_k(const double* __restrict__ st,
                           const float* __restrict__ gamma, const float* __restrict__ beta,
                           float* __restrict__ sc, float* __restrict__ bb)
{
    int c = threadIdx.x;
    if (c < 64) {
        double inv   = 1.0 / (double)M2;
        double mean  = st[c] * inv;
        double var   = st[64 + c] * inv - mean * mean;
        double scale = (double)gamma[c] / sqrt(var + 1e-5);
        sc[c] = (float)scale;
        bb[c] = (float)((double)beta[c] - mean * scale);
    }
}

__global__ void apply1_k(const float* __restrict__ t, const float* __restrict__ sc,
                         const float* __restrict__ bb)
{
    int i4 = blockIdx.x * blockDim.x + threadIdx.x;
    if (i4 >= M2 * 16) return;
    int c = (i4 & 15) * 4;
    float4 v = *(const float4*)(t + (size_t)i4 * 4);
    v.x = v.x * sc[c+0] + bb[c+0]; v.x = v.x >= 0.f ? v.x : 0.2f * v.x;
    v.y = v.y * sc[c+1] + bb[c+1]; v.y = v.y >= 0.f ? v.y : 0.2f * v.y;
    v.z = v.z * sc[c+2] + bb[c+2]; v.z = v.z >= 0.f ? v.z : 0.2f * v.z;
    v.w = v.w * sc[c+3] + bb[c+3]; v.w = v.w >= 0.f ? v.w : 0.2f * v.w;
    __nv_bfloat16 h0,l0,h1,l1,h2,l2,h3,l3;
    bsplit(v.x,h0,l0); bsplit(v.y,h1,l1); bsplit(v.z,h2,l2); bsplit(v.w,h3,l3);
    *(uint2*)(g_y1h + (size_t)i4 * 4) = make_uint2(pk2(h0,h1), pk2(h2,h3));
    *(uint2*)(g_y1l + (size_t)i4 * 4) = make_uint2(pk2(l0,l1), pk2(l2,l3));
}

__global__ void apply_out_k(const float* __restrict__ t, const float* __restrict__ sc,
                            const float* __restrict__ bb, float* __restrict__ out)
{
    int i4 = blockIdx.x * blockDim.x + threadIdx.x;
    if (i4 >= M2 * 16) return;
    int c = (i4 & 15) * 4;
    float4 v = *(const float4*)(t + (size_t)i4 * 4);
    v.x = v.x * sc[c+0] + bb[c+0]; v.x = v.x >= 0.f ? v.x : 0.2f * v.x;
    v.y = v.y * sc[c+1] + bb[c+1]; v.y = v.y >= 0.f ? v.y : 0.2f * v.y;
    v.z = v.z * sc[c+2] + bb[c+2]; v.z = v.z >= 0.f ? v.z : 0.2f * v.z;
    v.w = v.w * sc[c+3] + bb[c+3]; v.w = v.w >= 0.f ? v.w : 0.2f * v.w;
    *(float4*)(out + (size_t)i4 * 4) = v;
}

// ---------------- launch ----------------
extern "C" void kernel_launch(void* const* d_in, const int* in_sizes, int n_in,
                              void* d_out, int out_size)
{
    const float* x1    = (const float*)d_in[0];
    const float* x2    = (const float*)d_in[1];
    const int*   neigh = (const int*)  d_in[2];
    const int*   topI  = (const int*)  d_in[3];
    const int*   downI = (const int*)  d_in[4];
    const float* upB   = (const float*)d_in[6];
    const float* c1b   = (const float*)d_in[8];
    const float* gam1  = (const float*)d_in[9];
    const float* bet1  = (const float*)d_in[10];
    const float* c2b   = (const float*)d_in[12];
    const float* gam2  = (const float*)d_in[13];
    const float* bet2  = (const float*)d_in[14];
    float* out = (float*)d_out;

    __nv_bfloat16 *x1h, *x1l, *xh, *xl, *y1h, *y1l, *Wuh, *Wul, *W1h, *W1l, *W2h, *W2l;
    float *h, *t1, *t2, *sc1, *bb1, *sc2, *bb2;
    double *st;
    cudaGetSymbolAddress((void**)&x1h, g_x1h); cudaGetSymbolAddress((void**)&x1l, g_x1l);
    cudaGetSymbolAddress((void**)&h,   g_h);
    cudaGetSymbolAddress((void**)&xh,  g_xh);  cudaGetSymbolAddress((void**)&xl,  g_xl);
    cudaGetSymbolAddress((void**)&t1,  g_t1);
    cudaGetSymbolAddress((void**)&y1h, g_y1h); cudaGetSymbolAddress((void**)&y1l, g_y1l);
    cudaGetSymbolAddress((void**)&t2,  g_t2);
    cudaGetSymbolAddress((void**)&Wuh, g_Wuh); cudaGetSymbolAddress((void**)&Wul, g_Wul);
    cudaGetSymbolAddress((void**)&W1h, g_W1h); cudaGetSymbolAddress((void**)&W1l, g_W1l);
    cudaGetSymbolAddress((void**)&W2h, g_W2h); cudaGetSymbolAddress((void**)&W2l, g_W2l);
    cudaGetSymbolAddress((void**)&st,  g_st);
    cudaGetSymbolAddress((void**)&sc1, g_sc1); cudaGetSymbolAddress((void**)&bb1, g_bb1);
    cudaGetSymbolAddress((void**)&sc2, g_sc2); cudaGetSymbolAddress((void**)&bb2, g_bb2);

    cudaFuncSetAttribute(bf_gemm<128, 128, false>, cudaFuncAttributeMaxDynamicSharedMemorySize, SMEMSZ);
    cudaFuncSetAttribute(bf_gemm<896, 128, true>,  cudaFuncAttributeMaxDynamicSharedMemorySize, SMEMSZ);
    cudaFuncSetAttribute(bf_gemm<448, 64,  true>,  cudaFuncAttributeMaxDynamicSharedMemorySize, SMEMSZ);

    // 1) prep
    prep_k<<<2048, 256>>>(x1, (const float*)d_in[5], (const float*)d_in[7], (const float*)d_in[11]);
    // 2) up GEMM
    {
        dim3 grid(7, (M1 + 255) / 256);
        bf_gemm<128, 128, false><<<grid, 256, SMEMSZ>>>(x1h, x1l, Wuh, Wul, upB, h, M1, 448, nullptr);
    }
    // 3) build x
    build_x_k<<<(M2 * 32 + 255) / 256, 256>>>(h, x2, topI, downI);
    // 4) conv1
    {
        dim3 grid(1, (M2 + 255) / 256);
        bf_gemm<896, 128, true><<<grid, 256, SMEMSZ>>>(xh, xl, W1h, W1l, c1b, t1, M2, 64, neigh);
    }
    // 5-7) BN1 + activation
    stats_k<<<512, 256>>>(t1, st);
    finalize_k<<<1, 64>>>(st, gam1, bet1, sc1, bb1);
    apply1_k<<<(M2 * 16 + 255) / 256, 256>>>(t1, sc1, bb1);
    // 8) conv2
    {
        dim3 grid(1, (M2 + 255) / 256);
        bf_gemm<448, 64, true><<<grid, 256, SMEMSZ>>>(y1h, y1l, W2h, W2l, c2b, t2, M2, 64, neigh);
    }
    // 9-11) BN2 + output
    stats_k<<<512, 256>>>(t2, st + 128);
    finalize_k<<<1, 64>>>(st + 128, gam2, bet2, sc2, bb2);
    apply_out_k<<<(M2 * 16 + 255) / 256, 256>>>(t2, sc2, bb2, out);
}

// round 9
// speedup vs baseline: 1.6708x; 1.6708x over previous
#include <cuda_runtime.h>
#include <cuda_fp16.h>
#include <cstdint>

#define NRV  40962
#define NHV  163842
#define NR7V 286734
#define M1   81924
#define M2   327684

// ---------------- scratch ----------------
__device__ __half g_x1f[(size_t)M1*128];
__device__ __half g_hup[(size_t)M1*448];
__device__ __half g_xc [(size_t)M2*128];
__device__ float  g_t1 [(size_t)M2*64];
__device__ __half g_yc [(size_t)M2*64];
__device__ float  g_t2 [(size_t)M2*64];
__device__ __half g_Wu[128*448], g_W1[896*64], g_W2[448*64];
__device__ double g_st[256];
__device__ float  g_sc1[64], g_bb1[64], g_sc2[64], g_bb2[64];

// ---------------- PTX helpers ----------------
#define LDSM4(d0,d1,d2,d3,addr) \
    asm volatile("ldmatrix.sync.aligned.m8n8.x4.shared.b16 {%0,%1,%2,%3}, [%4];" \
                 : "=r"(d0),"=r"(d1),"=r"(d2),"=r"(d3) : "r"(addr))
#define LDSM4T(d0,d1,d2,d3,addr) \
    asm volatile("ldmatrix.sync.aligned.m8n8.x4.trans.shared.b16 {%0,%1,%2,%3}, [%4];" \
                 : "=r"(d0),"=r"(d1),"=r"(d2),"=r"(d3) : "r"(addr))
#define MMA_F16(c,a0,a1,a2,a3,b0,b1) \
    asm volatile("mma.sync.aligned.m16n8k16.row.col.f32.f16.f16.f32 " \
                 "{%0,%1,%2,%3}, {%4,%5,%6,%7}, {%8,%9}, {%0,%1,%2,%3};" \
                 : "+f"(c[0]),"+f"(c[1]),"+f"(c[2]),"+f"(c[3]) \
                 : "r"(a0),"r"(a1),"r"(a2),"r"(a3),"r"(b0),"r"(b1))

__device__ __forceinline__ void cpa16(uint32_t d, const void* s) {
    asm volatile("cp.async.ca.shared.global [%0], [%1], 16;" :: "r"(d), "l"(s) : "memory");
}
#define CP_COMMIT() asm volatile("cp.async.commit_group;" ::: "memory")
#define CP_WAIT2()  asm volatile("cp.async.wait_group 2;" ::: "memory")

__device__ __forceinline__ void st2(float* p, float a, float b) {
    *(float2*)p = make_float2(a, b);
}
__device__ __forceinline__ void st2(__half* p, float a, float b) {
    *(__half2*)p = __floats2half2_rn(a, b);
}

// smem per stage (14336 B): A [0,10240) 128 rows pitch 80 (64B data);
//                           B [10240,14336) 32 k-rows x 128B, XOR-swizzled
#define STG16  14336
#define SMEMSZ (4 * STG16)

// ---------------- 4-deep pipelined fp16 HMMA GEMM ----------------
// out[Mtot x Ntot] = gatherA[Mtot x K] @ W[K x Ntot] + bias
// CTA 256 thr, tile 128(M) x 64(N); warp (wr,wc) covers 32x32.
template<int K, int SEG, bool GATHER, typename OutT>
__global__ __launch_bounds__(256, 3)
void h_gemm(const __half* __restrict__ A, const __half* __restrict__ B,
            const float* __restrict__ bias, OutT* __restrict__ out,
            int Mtot, int Ntot, const int* __restrict__ neigh)
{
    extern __shared__ __align__(128) uint8_t sm[];
    constexpr int NC = K / 32;
    const uint32_t smA = (uint32_t)__cvta_generic_to_shared(sm);
    const int tid = threadIdx.x;
    const int colBase = blockIdx.x * 64;
    const int rowCTA  = blockIdx.y * 128;

    // ---- loader roles ----
    const int arow = tid >> 1, ahalf = tid & 1;     // A: 2 thr/row, 32B each
    const int gr   = rowCTA + arow;
    const int grC  = gr < Mtot ? gr : Mtot - 1;
    int bOff = 0, n7 = 0;
    if (GATHER) { bOff = (grC >= NHV) ? NHV : 0; n7 = (grC - bOff) * 7; }
    const int bk = tid >> 3;                        // B k-row 0..31
    const int bg = tid & 7;                         // 16B chunk
    const uint32_t aD = smA + arow * 80 + ahalf * 32;
    const uint32_t bD = smA + 10240 + bk * 128 + 16 * (bg ^ (bk & 7));

#define ISSUE(c_) do { \
        const uint32_t so_ = ((c_) & 3) * STG16; \
        int seg_, coff_; \
        if (SEG == 128) { seg_ = (c_) >> 2; coff_ = ((c_) & 3) * 32; } \
        else            { seg_ = (c_) >> 1; coff_ = ((c_) & 1) * 32; } \
        size_t src_ = GATHER ? (size_t)(bOff + neigh[n7 + seg_]) : (size_t)grC; \
        const __half* pa_ = A + src_ * SEG + coff_ + ahalf * 16; \
        cpa16(aD + so_,      pa_); \
        cpa16(aD + so_ + 16, pa_ + 8); \
        const __half* pb_ = B + (size_t)((c_) * 32 + bk) * Ntot + colBase + bg * 8; \
        cpa16(bD + so_, pb_); \
    } while (0)

    // ---- compute roles ----
    const int lane = tid & 31, w = tid >> 5;
    const int wr = w & 3, wc = w >> 2;
    const uint32_t aL = smA + (wr * 32 + (lane & 15)) * 80 + (lane >> 4) * 16;
    const int nH  = lane >> 4;
    const int krl = lane & 15;
    const int swz = krl & 7;

    float acc[2][4][4];
#pragma unroll
    for (int a = 0; a < 2; a++)
#pragma unroll
        for (int b = 0; b < 4; b++)
#pragma unroll
            for (int q = 0; q < 4; q++) acc[a][b][q] = 0.f;

    // prologue: 3 stages in flight
    ISSUE(0); CP_COMMIT();
    ISSUE(1); CP_COMMIT();
    ISSUE(2); CP_COMMIT();

#pragma unroll 1
    for (int c = 0; c < NC; c++) {
        CP_WAIT2();
        __syncthreads();

        const uint32_t so = (c & 3) * STG16;
#pragma unroll
        for (int kk = 0; kk < 2; kk++) {
            uint32_t a0[4], a1[4];
            {
                uint32_t aAddr = aL + so + kk * 32;
                LDSM4(a0[0], a0[1], a0[2], a0[3], aAddr);
                LDSM4(a1[0], a1[1], a1[2], a1[3], aAddr + 16 * 80);
            }
            const uint32_t bRow = smA + so + 10240 + (kk * 16 + krl) * 128;
#pragma unroll
            for (int bt = 0; bt < 2; bt++) {
                const int nt = wc * 2 + bt;
                uint32_t b0, b1, b2, b3;
                LDSM4T(b0, b1, b2, b3, bRow + 16 * ((2 * nt + nH) ^ swz));
                MMA_F16(acc[0][2*bt],   a0[0],a0[1],a0[2],a0[3], b0,b1);
                MMA_F16(acc[0][2*bt+1], a0[0],a0[1],a0[2],a0[3], b2,b3);
                MMA_F16(acc[1][2*bt],   a1[0],a1[1],a1[2],a1[3], b0,b1);
                MMA_F16(acc[1][2*bt+1], a1[0],a1[1],a1[2],a1[3], b2,b3);
            }
        }
        if (c + 3 < NC) ISSUE(c + 3);
        CP_COMMIT();
    }
#undef ISSUE

    // ---- epilogue ----
    const int gid = lane >> 2, tig = lane & 3;
#pragma unroll
    for (int mh = 0; mh < 2; mh++) {
        const int r0 = rowCTA + wr * 32 + mh * 16 + gid;
#pragma unroll
        for (int j = 0; j < 4; j++) {
            const int col = colBase + wc * 32 + j * 8 + tig * 2;
            const float b0 = bias[col], b1 = bias[col + 1];
            if (r0 < Mtot)
                st2(out + (size_t)r0 * Ntot + col, acc[mh][j][0] + b0, acc[mh][j][1] + b1);
            if (r0 + 8 < Mtot)
                st2(out + (size_t)(r0 + 8) * Ntot + col, acc[mh][j][2] + b0, acc[mh][j][3] + b1);
        }
    }
}

// ---------------- aux kernels ----------------
__global__ void prep_k(const float* __restrict__ x1, const float* __restrict__ upW,
                       const float* __restrict__ c1W, const float* __restrict__ c2W)
{
    int i = blockIdx.x * blockDim.x + threadIdx.x;
    if (i < 256) g_st[i] = 0.0;
    const int stride = gridDim.x * blockDim.x;
    for (int t = i; t < M1 * 32; t += stride) {
        float4 v = ((const float4*)x1)[t];
        ((__half2*)g_x1f)[t*2]   = __floats2half2_rn(v.x, v.y);
        ((__half2*)g_x1f)[t*2+1] = __floats2half2_rn(v.z, v.w);
    }
    for (int t = i; t < 128 * 448 / 4; t += stride) {
        float4 v = ((const float4*)upW)[t];
        ((__half2*)g_Wu)[t*2]   = __floats2half2_rn(v.x, v.y);
        ((__half2*)g_Wu)[t*2+1] = __floats2half2_rn(v.z, v.w);
    }
    for (int t = i; t < 896 * 64 / 4; t += stride) {
        float4 v = ((const float4*)c1W)[t];
        ((__half2*)g_W1)[t*2]   = __floats2half2_rn(v.x, v.y);
        ((__half2*)g_W1)[t*2+1] = __floats2half2_rn(v.z, v.w);
    }
    for (int t = i; t < 448 * 64 / 4; t += stride) {
        float4 v = ((const float4*)c2W)[t];
        ((__half2*)g_W2)[t*2]   = __floats2half2_rn(v.x, v.y);
        ((__half2*)g_W2)[t*2+1] = __floats2half2_rn(v.z, v.w);
    }
}

// x = concat(upsample(h), x2) -> fp16 [B*NH, 128]
__global__ void build_x_k(const float* __restrict__ x2,
                          const int* __restrict__ topIdx, const int* __restrict__ downIdx)
{
    int idx = blockIdx.x * 256 + threadIdx.x;
    if (idx >= M2 * 32) return;
    int row = idx >> 5, q = idx & 31;
    int b = (row >= NHV) ? 1 : 0;
    int n = row - b * NHV;
    size_t o = (size_t)row * 128 + q * 4;
    if (q < 16) {
        int c = q * 4;
        if (n < NRV) {
            uint2 v = *(const uint2*)(g_hup + ((size_t)b * NR7V + topIdx[n]) * 64 + c);
            *(uint2*)(g_xc + o) = v;
        } else {
            int m = n - NRV;
            const __half2* p0 = (const __half2*)(g_hup + ((size_t)b * NR7V + downIdx[2*m])   * 64 + c);
            const __half2* p1 = (const __half2*)(g_hup + ((size_t)b * NR7V + downIdx[2*m+1]) * 64 + c);
            float2 a0 = __half22float2(p0[0]), a1 = __half22float2(p0[1]);
            float2 c0 = __half22float2(p1[0]), c1 = __half22float2(p1[1]);
            ((__half2*)(g_xc + o))[0] = __floats2half2_rn(0.5f*(a0.x+c0.x), 0.5f*(a0.y+c0.y));
            ((__half2*)(g_xc + o))[1] = __floats2half2_rn(0.5f*(a1.x+c1.x), 0.5f*(a1.y+c1.y));
        }
    } else {
        float4 v = *(const float4*)(x2 + (size_t)row * 64 + (q - 16) * 4);
        ((__half2*)(g_xc + o))[0] = __floats2half2_rn(v.x, v.y);
        ((__half2*)(g_xc + o))[1] = __floats2half2_rn(v.z, v.w);
    }
}

__global__ void stats_k(const float* __restrict__ t, double* __restrict__ st)
{
    int c   = threadIdx.x & 63;
    int sub = threadIdx.x >> 6;
    double s = 0.0, sq = 0.0;
    for (int r = blockIdx.x * 4 + sub; r < M2; r += gridDim.x * 4) {
        float v = t[(size_t)r * 64 + c];
        s += v; sq += (double)v * (double)v;
    }
    __shared__ double sh[512];
    sh[threadIdx.x] = s; sh[256 + threadIdx.x] = sq;
    __syncthreads();
    if (sub == 0) {
#pragma unroll
        for (int i = 1; i < 4; i++) { s += sh[c + 64 * i]; sq += sh[256 + c + 64 * i]; }
        atomicAdd(&st[c], s);
        atomicAdd(&st[64 + c], sq);
    }
}

__global__ void finalize_k(const double* __restrict__ st,
                           const float* __restrict__ gamma, const float* __restrict__ beta,
                           float* __restrict__ sc, float* __restrict__ bb)
{
    int c = threadIdx.x;
    if (c < 64) {
        double inv   = 1.0 / (double)M2;
        double mean  = st[c] * inv;
        double var   = st[64 + c] * inv - mean * mean;
        double scale = (double)gamma[c] / sqrt(var + 1e-5);
        sc[c] = (float)scale;
        bb[c] = (float)((double)beta[c] - mean * scale);
    }
}

// y = lrelu(bn1(t1)) -> fp16
__global__ void apply1_k(const float* __restrict__ t, const float* __restrict__ sc,
                         const float* __restrict__ bb)
{
    int i4 = blockIdx.x * blockDim.x + threadIdx.x;
    if (i4 >= M2 * 16) return;
    int c = (i4 & 15) * 4;
    float4 v = *(const float4*)(t + (size_t)i4 * 4);
    v.x = v.x * sc[c+0] + bb[c+0]; v.x = v.x >= 0.f ? v.x : 0.2f * v.x;
    v.y = v.y * sc[c+1] + bb[c+1]; v.y = v.y >= 0.f ? v.y : 0.2f * v.y;
    v.z = v.z * sc[c+2] + bb[c+2]; v.z = v.z >= 0.f ? v.z : 0.2f * v.z;
    v.w = v.w * sc[c+3] + bb[c+3]; v.w = v.w >= 0.f ? v.w : 0.2f * v.w;
    ((__half2*)g_yc)[i4*2]   = __floats2half2_rn(v.x, v.y);
    ((__half2*)g_yc)[i4*2+1] = __floats2half2_rn(v.z, v.w);
}

__global__ void apply_out_k(const float* __restrict__ t, const float* __restrict__ sc,
                            const float* __restrict__ bb, float* __restrict__ out)
{
    int i4 = blockIdx.x * blockDim.x + threadIdx.x;
    if (i4 >= M2 * 16) return;
    int c = (i4 & 15) * 4;
    float4 v = *(const float4*)(t + (size_t)i4 * 4);
    v.x = v.x * sc[c+0] + bb[c+0]; v.x = v.x >= 0.f ? v.x : 0.2f * v.x;
    v.y = v.y * sc[c+1] + bb[c+1]; v.y = v.y >= 0.f ? v.y : 0.2f * v.y;
    v.z = v.z * sc[c+2] + bb[c+2]; v.z = v.z >= 0.f ? v.z : 0.2f * v.z;
    v.w = v.w * sc[c+3] + bb[c+3]; v.w = v.w >= 0.f ? v.w : 0.2f * v.w;
    *(float4*)(out + (size_t)i4 * 4) = v;
}

// ---------------- launch ----------------
extern "C" void kernel_launch(void* const* d_in, const int* in_sizes, int n_in,
                              void* d_out, int out_size)
{
    const float* x1    = (const float*)d_in[0];
    const float* x2    = (const float*)d_in[1];
    const int*   neigh = (const int*)  d_in[2];
    const int*   topI  = (const int*)  d_in[3];
    const int*   downI = (const int*)  d_in[4];
    const float* upB   = (const float*)d_in[6];
    const float* c1b   = (const float*)d_in[8];
    const float* gam1  = (const float*)d_in[9];
    const float* bet1  = (const float*)d_in[10];
    const float* c2b   = (const float*)d_in[12];
    const float* gam2  = (const float*)d_in[13];
    const float* bet2  = (const float*)d_in[14];
    float* out = (float*)d_out;

    __half *x1f, *hup, *xc, *yc, *Wu, *W1, *W2;
    float *t1, *t2, *sc1, *bb1, *sc2, *bb2;
    double *st;
    cudaGetSymbolAddress((void**)&x1f, g_x1f);
    cudaGetSymbolAddress((void**)&hup, g_hup);
    cudaGetSymbolAddress((void**)&xc,  g_xc);
    cudaGetSymbolAddress((void**)&t1,  g_t1);
    cudaGetSymbolAddress((void**)&yc,  g_yc);
    cudaGetSymbolAddress((void**)&t2,  g_t2);
    cudaGetSymbolAddress((void**)&Wu,  g_Wu);
    cudaGetSymbolAddress((void**)&W1,  g_W1);
    cudaGetSymbolAddress((void**)&W2,  g_W2);
    cudaGetSymbolAddress((void**)&st,  g_st);
    cudaGetSymbolAddress((void**)&sc1, g_sc1); cudaGetSymbolAddress((void**)&bb1, g_bb1);
    cudaGetSymbolAddress((void**)&sc2, g_sc2); cudaGetSymbolAddress((void**)&bb2, g_bb2);

    cudaFuncSetAttribute((const void*)h_gemm<128, 128, false, __half>,
                         cudaFuncAttributeMaxDynamicSharedMemorySize, SMEMSZ);
    cudaFuncSetAttribute((const void*)h_gemm<896, 128, true, float>,
                         cudaFuncAttributeMaxDynamicSharedMemorySize, SMEMSZ);
    cudaFuncSetAttribute((const void*)h_gemm<448, 64, true, float>,
                         cudaFuncAttributeMaxDynamicSharedMemorySize, SMEMSZ);

    // 1) prep: fp16 conversions + zero stats
    prep_k<<<1024, 256>>>(x1, (const float*)d_in[5], (const float*)d_in[7], (const float*)d_in[11]);
    // 2) up GEMM: [81924 x 128] @ [128 x 448] + up_b -> hup (fp16)
    {
        dim3 grid(7, (M1 + 127) / 128);
        h_gemm<128, 128, false, __half><<<grid, 256, SMEMSZ>>>(x1f, Wu, upB, hup, M1, 448, nullptr);
    }
    // 3) build x (fp16 concat)
    build_x_k<<<(M2 * 32 + 255) / 256, 256>>>(x2, topI, downI);
    // 4) conv1: gather [327684 x 896] @ [896 x 64] + b -> t1
    {
        dim3 grid(1, (M2 + 127) / 128);
        h_gemm<896, 128, true, float><<<grid, 256, SMEMSZ>>>(xc, W1, c1b, t1, M2, 64, neigh);
    }
    // 5-7) BN1 + activation
    stats_k<<<512, 256>>>(t1, st);
    finalize_k<<<1, 64>>>(st, gam1, bet1, sc1, bb1);
    apply1_k<<<(M2 * 16 + 255) / 256, 256>>>(t1, sc1, bb1);
    // 8) conv2: gather [327684 x 448] @ [448 x 64] + b -> t2
    {
        dim3 grid(1, (M2 + 127) / 128);
        h_gemm<448, 64, true, float><<<grid, 256, SMEMSZ>>>(yc, W2, c2b, t2, M2, 64, neigh);
    }
    // 9-11) BN2 + output
    stats_k<<<512, 256>>>(t2, st + 128);
    finalize_k<<<1, 64>>>(st + 128, gam2, bet2, sc2, bb2);
    apply_out_k<<<(M2 * 16 + 255) / 256, 256>>>(t2, sc2, bb2, out);
}